// round 2
// baseline (speedup 1.0000x reference)
#include <cuda_runtime.h>
#include <math.h>

#define PI_F 3.14159265358979323846f
#define NS_MAX 524288
#define NR_MAX 16384

// ---------------- device scratch ----------------
__device__ float g_Wg1T[256 * 256];
__device__ float g_Wg0T[256 * 40];
__device__ float g_Wc1p[256 * 4];
__device__ float g_bc1p[4];
__device__ float g_a[NS_MAX];
__device__ float g_loga[NS_MAX];
__device__ float g_rgb[NS_MAX * 3];
__device__ float g_nrm[NS_MAX * 3];
__device__ int   g_start[NR_MAX + 1];

// ---------------- smem layout (floats) ----------------
#define XS_OFF   0
#define H0_OFF   2560
#define H1_OFF   18944
#define WS_OFF   35328
#define FS_OFF   39552
#define GX_OFF   40576
#define RGB_OFF  43136
#define PS_OFF   43392
#define DS_OFF   43584
#define NSM_OFF  43776
#define CIN_OFF  43968
#define SMEM_FLOATS 45568
#define SMEM_BYTES (SMEM_FLOATS * 4)

// ---------------- block GEMM: D[C][64] = epi(A[K][64]^T @ W[K][C]) ----------------
// EPI 0: relu(acc+b)   1: (D>0?acc:0) in-place mask   2: acc+b   3: sigmoid(acc+b)
template <int EPI>
__device__ void block_gemm(const float* As, const float* Wg, int ldw,
                           int K, int C, const float* bias,
                           float* Ds, float* Ws) {
    const int tid = threadIdx.x;
    const int tx = tid & 15;
    const int ty = tid >> 4;
    for (int c0 = 0; c0 < C; c0 += 128) {
        float acc[4][8];
#pragma unroll
        for (int i = 0; i < 4; i++)
#pragma unroll
            for (int j = 0; j < 8; j++) acc[i][j] = 0.f;

        const int ntiles = (K + 31) >> 5;
        float4 pre[4];
#pragma unroll
        for (int q = 0; q < 4; q++) {
            int idx = q * 256 + tid, r = idx >> 5, c4 = idx & 31;
            float4 v = make_float4(0.f, 0.f, 0.f, 0.f);
            int cc = c0 + c4 * 4;
            if (r < K && cc < C) v = *reinterpret_cast<const float4*>(Wg + (size_t)r * ldw + cc);
            pre[q] = v;
        }
        for (int t = 0; t < ntiles; ++t) {
            __syncthreads();
#pragma unroll
            for (int q = 0; q < 4; q++) {
                int idx = q * 256 + tid, r = idx >> 5, c4 = idx & 31;
                *reinterpret_cast<float4*>(Ws + r * 132 + c4 * 4) = pre[q];
            }
            __syncthreads();
            if (t + 1 < ntiles) {
                int k0 = (t + 1) * 32;
#pragma unroll
                for (int q = 0; q < 4; q++) {
                    int idx = q * 256 + tid, r = idx >> 5, c4 = idx & 31;
                    float4 v = make_float4(0.f, 0.f, 0.f, 0.f);
                    int cc = c0 + c4 * 4;
                    if (k0 + r < K && cc < C)
                        v = *reinterpret_cast<const float4*>(Wg + (size_t)(k0 + r) * ldw + cc);
                    pre[q] = v;
                }
            }
            int klen = K - t * 32; if (klen > 32) klen = 32;
            const float* Ap = As + t * 32 * 64 + tx * 4;
            const float* Wp = Ws + ty * 8;
            for (int kt = 0; kt < klen; ++kt) {
                float4 a  = *reinterpret_cast<const float4*>(Ap + kt * 64);
                float4 w0 = *reinterpret_cast<const float4*>(Wp + kt * 132);
                float4 w1 = *reinterpret_cast<const float4*>(Wp + kt * 132 + 4);
                float av[4] = {a.x, a.y, a.z, a.w};
                float wv[8] = {w0.x, w0.y, w0.z, w0.w, w1.x, w1.y, w1.z, w1.w};
#pragma unroll
                for (int i = 0; i < 4; i++)
#pragma unroll
                    for (int j = 0; j < 8; j++)
                        acc[i][j] = fmaf(av[i], wv[j], acc[i][j]);
            }
        }
        __syncthreads();
#pragma unroll
        for (int j = 0; j < 8; j++) {
            int c = c0 + ty * 8 + j;
            if (c < C) {
                float4 v;
                if (EPI == 1) {
                    float4 d = *reinterpret_cast<const float4*>(Ds + c * 64 + tx * 4);
                    v.x = d.x > 0.f ? acc[0][j] : 0.f;
                    v.y = d.y > 0.f ? acc[1][j] : 0.f;
                    v.z = d.z > 0.f ? acc[2][j] : 0.f;
                    v.w = d.w > 0.f ? acc[3][j] : 0.f;
                } else {
                    float b = bias ? bias[c] : 0.f;
                    v.x = acc[0][j] + b; v.y = acc[1][j] + b;
                    v.z = acc[2][j] + b; v.w = acc[3][j] + b;
                    if (EPI == 0) {
                        v.x = fmaxf(v.x, 0.f); v.y = fmaxf(v.y, 0.f);
                        v.z = fmaxf(v.z, 0.f); v.w = fmaxf(v.w, 0.f);
                    } else if (EPI == 3) {
                        v.x = 1.f / (1.f + expf(-v.x)); v.y = 1.f / (1.f + expf(-v.y));
                        v.z = 1.f / (1.f + expf(-v.z)); v.w = 1.f / (1.f + expf(-v.w));
                    }
                }
                *reinterpret_cast<float4*>(Ds + c * 64 + tx * 4) = v;
            }
        }
    }
    __syncthreads();
}

// ---------------- K0: weight prep ----------------
__global__ void prep_weights(const float* __restrict__ Wg0, const float* __restrict__ Wg1,
                             const float* __restrict__ Wc1, const float* __restrict__ bc1) {
    int idx = blockIdx.x * 256 + threadIdx.x;   // 65536 threads
    g_Wg1T[idx] = Wg1[(idx & 255) * 256 + (idx >> 8)];
    if (idx < 10240) {
        int k = idx / 40, r = idx % 40;
        g_Wg0T[idx] = (r < 39) ? Wg0[r * 256 + k] : 0.f;
    }
    if (idx < 1024) {
        int k = idx >> 2, c = idx & 3;
        g_Wc1p[idx] = (c < 3) ? Wc1[k * 3 + c] : 0.f;
    }
    if (idx < 4) g_bc1p[idx] = (idx < 3) ? bc1[idx] : 0.f;
}

// ---------------- K1: fused per-sample pipeline ----------------
template <bool RAND>
__global__ void __launch_bounds__(256) fused_mlp(
    const float* __restrict__ rays_o, const float* __restrict__ rays_d,
    const int* __restrict__ ridx, const float* __restrict__ t_starts,
    const float* __restrict__ pts, const float* __restrict__ s_var,
    const float* __restrict__ Wg0, const float* __restrict__ bg0,
    const float* __restrict__ Wg1, const float* __restrict__ bg1,
    const float* __restrict__ Wg2, const float* __restrict__ bg2,
    const float* __restrict__ Wc0, const float* __restrict__ bc0,
    float* __restrict__ out, int n, long long off_sdf) {
    extern __shared__ float sm[];
    float* XS  = sm + XS_OFF;
    float* H0s = sm + H0_OFF;
    float* H1s = sm + H1_OFF;
    float* WS  = sm + WS_OFF;
    float* FS  = sm + FS_OFF;
    float* GX  = sm + GX_OFF;
    float* RGB = sm + RGB_OFF;
    float* PS  = sm + PS_OFF;
    float* DSH = sm + DS_OFF;
    float* NSM = sm + NSM_OFF;
    float* CIN = sm + CIN_OFF;

    const int tid = threadIdx.x;
    const int s0 = blockIdx.x * 64;
    const int s  = s0 + tid;
    const bool valid = (tid < 64) && (s < n);

    if (tid < 64) {
        int si = (s < n) ? s : (n - 1);
        float px, py, pz;
        if (RAND) {
            px = pts[si * 3 + 0]; py = pts[si * 3 + 1]; pz = pts[si * 3 + 2];
        } else {
            int ray = ridx[si];
            float ox = rays_o[ray * 3 + 0], oy = rays_o[ray * 3 + 1], oz = rays_o[ray * 3 + 2];
            float dx = rays_d[ray * 3 + 0], dy = rays_d[ray * 3 + 1], dz = rays_d[ray * 3 + 2];
            float inv = 1.f / (sqrtf(dx * dx + dy * dy + dz * dz) + 1e-10f);
            dx *= inv; dy *= inv; dz *= inv;
            float mid = t_starts[si] + 0.0025f;
            px = fmaf(dx, mid, ox); py = fmaf(dy, mid, oy); pz = fmaf(dz, mid, oz);
            PS[tid] = px; PS[64 + tid] = py; PS[128 + tid] = pz;
            DSH[tid] = dx; DSH[64 + tid] = dy; DSH[128 + tid] = dz;
        }
        XS[tid] = px; XS[64 + tid] = py; XS[128 + tid] = pz;
        float f = PI_F;
#pragma unroll
        for (int i = 0; i < 6; i++) {
            float sx, cx, sy, cy, sz, cz;
            sincosf(f * px, &sx, &cx);
            sincosf(f * py, &sy, &cy);
            sincosf(f * pz, &sz, &cz);
            XS[(3 + 6 * i) * 64 + tid] = sx;
            XS[(4 + 6 * i) * 64 + tid] = sy;
            XS[(5 + 6 * i) * 64 + tid] = sz;
            XS[(6 + 6 * i) * 64 + tid] = cx;
            XS[(7 + 6 * i) * 64 + tid] = cy;
            XS[(8 + 6 * i) * 64 + tid] = cz;
            f *= 2.f;
        }
    }
    __syncthreads();

    block_gemm<0>(XS,  Wg0, 256, 39, 256, bg0, H0s, WS);
    block_gemm<0>(H0s, Wg1, 256, 256, 256, bg1, H1s, WS);
    block_gemm<2>(H1s, Wg2, 16, 256, 16, bg2, FS, WS);

    if (RAND) {
        if (valid) out[off_sdf + s] = FS[tid];
        return;
    }

    // g1 = (h1>0) ? Wg2[:,0] : 0  (in place in H1s)
    for (int idx = tid; idx < 256 * 64; idx += 256)
        H1s[idx] = (H1s[idx] > 0.f) ? Wg2[(idx >> 6) * 16] : 0.f;
    __syncthreads();

    block_gemm<1>(H1s, g_Wg1T, 256, 256, 256, 0, H0s, WS);   // g0 masked by h0>0
    block_gemm<2>(H0s, g_Wg0T, 40, 256, 39, 0, GX, WS);      // grad wrt posenc

    float inv_s = fminf(fmaxf(expf(s_var[0]), 1e-6f), 1e6f);
    if (tid < 64) {
        float gp[3];
#pragma unroll
        for (int d = 0; d < 3; d++) {
            float g = GX[d * 64 + tid];
            float f = PI_F;
#pragma unroll
            for (int i = 0; i < 6; i++) {
                float sn = XS[(3 + 6 * i + d) * 64 + tid];
                float cs = XS[(6 + 6 * i + d) * 64 + tid];
                float gs = GX[(3 + 6 * i + d) * 64 + tid];
                float gc = GX[(6 + 6 * i + d) * 64 + tid];
                g += f * (cs * gs - sn * gc);
                f *= 2.f;
            }
            gp[d] = g;
        }
        float len = sqrtf(gp[0] * gp[0] + gp[1] * gp[1] + gp[2] * gp[2]);
        float ninv = 1.f / (len + 1e-10f);
        float nx = gp[0] * ninv, ny = gp[1] * ninv, nz = gp[2] * ninv;
        NSM[tid] = nx; NSM[64 + tid] = ny; NSM[128 + tid] = nz;

        float dx = DSH[tid], dy = DSH[64 + tid], dz = DSH[128 + tid];
        float dsdf = fminf(gp[0] * dx + gp[1] * dy + gp[2] * dz, 0.f);
        float sdf = FS[tid];
        float cdf = 1.f / (1.f + expf(-inv_s * sdf));
        float rho = fmaxf(inv_s * (cdf - 1.f) * dsdf, 0.f);
        float alpha = 1.f - expf(-rho * 0.005f);
        float a = fminf(fmaxf(alpha, 0.f), 1.f - 1e-7f);
        if (valid) {
            g_a[s] = a;
            g_loga[s] = log1pf(-a);
            g_nrm[s * 3 + 0] = nx; g_nrm[s * 3 + 1] = ny; g_nrm[s * 3 + 2] = nz;
            out[off_sdf + s] = sdf;
        }
        // cin = [dir(3), feats(16), points(3), normal(3)]
        CIN[0 * 64 + tid] = dx; CIN[1 * 64 + tid] = dy; CIN[2 * 64 + tid] = dz;
#pragma unroll
        for (int c = 0; c < 16; c++) CIN[(3 + c) * 64 + tid] = FS[c * 64 + tid];
        CIN[19 * 64 + tid] = PS[tid]; CIN[20 * 64 + tid] = PS[64 + tid]; CIN[21 * 64 + tid] = PS[128 + tid];
        CIN[22 * 64 + tid] = nx; CIN[23 * 64 + tid] = ny; CIN[24 * 64 + tid] = nz;
    }
    __syncthreads();

    block_gemm<0>(CIN, Wc0, 256, 25, 256, bc0, H1s, WS);
    block_gemm<3>(H1s, g_Wc1p, 4, 256, 4, g_bc1p, RGB, WS);

    if (valid) {
        g_rgb[s * 3 + 0] = RGB[0 * 64 + tid];
        g_rgb[s * 3 + 1] = RGB[1 * 64 + tid];
        g_rgb[s * 3 + 2] = RGB[2 * 64 + tid];
    }
}

// ---------------- K2: ray start offsets ----------------
__global__ void ray_starts(const int* __restrict__ ridx, int n_rays, int n_samples) {
    int r = blockIdx.x * 256 + threadIdx.x;
    if (r > n_rays) return;
    int lo = 0, hi = n_samples;
    while (lo < hi) { int m = (lo + hi) >> 1; if (ridx[m] < r) lo = m + 1; else hi = m; }
    g_start[r] = lo;
}

// ---------------- K3: per-ray scan + composite (warp per ray) ----------------
__global__ void composite(const float* __restrict__ t_starts, float* __restrict__ out,
                          int n_rays, long long off_c, long long off_n,
                          long long off_o, long long off_d, long long off_w) {
    int ray = (blockIdx.x * blockDim.x + threadIdx.x) >> 5;
    int lane = threadIdx.x & 31;
    if (ray >= n_rays) return;
    int s0 = g_start[ray], s1 = g_start[ray + 1];
    float carry = 0.f, op = 0.f, dep = 0.f;
    float c0 = 0.f, c1 = 0.f, c2 = 0.f, n0 = 0.f, n1 = 0.f, n2 = 0.f;
    for (int base = s0; base < s1; base += 32) {
        int s = base + lane;
        bool v = s < s1;
        float lg = v ? g_loga[s] : 0.f;
        float incl = lg;
#pragma unroll
        for (int o = 1; o < 32; o <<= 1) {
            float t = __shfl_up_sync(0xffffffffu, incl, o);
            if (lane >= o) incl += t;
        }
        if (v) {
            float w = g_a[s] * expf(carry + incl - lg);
            out[off_w + s] = w;
            float mid = t_starts[s] + 0.0025f;
            op += w; dep += w * mid;
            c0 += w * g_rgb[s * 3 + 0]; c1 += w * g_rgb[s * 3 + 1]; c2 += w * g_rgb[s * 3 + 2];
            n0 += w * g_nrm[s * 3 + 0]; n1 += w * g_nrm[s * 3 + 1]; n2 += w * g_nrm[s * 3 + 2];
        }
        carry += __shfl_sync(0xffffffffu, incl, 31);
    }
#pragma unroll
    for (int o = 16; o; o >>= 1) {
        op += __shfl_xor_sync(0xffffffffu, op, o);
        dep += __shfl_xor_sync(0xffffffffu, dep, o);
        c0 += __shfl_xor_sync(0xffffffffu, c0, o);
        c1 += __shfl_xor_sync(0xffffffffu, c1, o);
        c2 += __shfl_xor_sync(0xffffffffu, c2, o);
        n0 += __shfl_xor_sync(0xffffffffu, n0, o);
        n1 += __shfl_xor_sync(0xffffffffu, n1, o);
        n2 += __shfl_xor_sync(0xffffffffu, n2, o);
    }
    if (lane == 0) {
        out[off_o + ray] = op;
        out[off_d + ray] = dep;
        out[off_c + ray * 3 + 0] = c0; out[off_c + ray * 3 + 1] = c1; out[off_c + ray * 3 + 2] = c2;
        float nl = sqrtf(n0 * n0 + n1 * n1 + n2 * n2);
        float ninv = 1.f / (nl + 1e-10f);
        out[off_n + ray * 3 + 0] = n0 * ninv;
        out[off_n + ray * 3 + 1] = n1 * ninv;
        out[off_n + ray * 3 + 2] = n2 * ninv;
    }
}

extern "C" void kernel_launch(void* const* d_in, const int* in_sizes, int n_in,
                              void* d_out, int out_size) {
    const float* rays_o = (const float*)d_in[0];
    const float* rays_d = (const float*)d_in[1];
    const int*   ridx   = (const int*)d_in[2];
    const float* t_st   = (const float*)d_in[3];
    const float* rpts   = (const float*)d_in[4];
    const float* s_var  = (const float*)d_in[5];
    const float* Wg0 = (const float*)d_in[6];  const float* bg0 = (const float*)d_in[7];
    const float* Wg1 = (const float*)d_in[8];  const float* bg1 = (const float*)d_in[9];
    const float* Wg2 = (const float*)d_in[10]; const float* bg2 = (const float*)d_in[11];
    const float* Wc0 = (const float*)d_in[12]; const float* bc0 = (const float*)d_in[13];
    const float* Wc1 = (const float*)d_in[14]; const float* bc1 = (const float*)d_in[15];
    float* out = (float*)d_out;

    int n_rays = in_sizes[0] / 3;
    int n_samples = in_sizes[2];
    int n_rand = in_sizes[4] / 3;

    long long off_c = 0;
    long long off_n = off_c + 3LL * n_rays;
    long long off_o = off_n + 3LL * n_rays;
    long long off_d = off_o + n_rays;
    long long off_w = off_d + n_rays;
    long long off_s = off_w + n_samples;
    long long off_r = off_s + n_samples;

    cudaFuncSetAttribute(fused_mlp<false>, cudaFuncAttributeMaxDynamicSharedMemorySize, SMEM_BYTES);
    cudaFuncSetAttribute(fused_mlp<true>,  cudaFuncAttributeMaxDynamicSharedMemorySize, SMEM_BYTES);

    prep_weights<<<256, 256>>>(Wg0, Wg1, Wc1, bc1);
    fused_mlp<false><<<(n_samples + 63) / 64, 256, SMEM_BYTES>>>(
        rays_o, rays_d, ridx, t_st, rpts, s_var,
        Wg0, bg0, Wg1, bg1, Wg2, bg2, Wc0, bc0, out, n_samples, off_s);
    fused_mlp<true><<<(n_rand + 63) / 64, 256, SMEM_BYTES>>>(
        rays_o, rays_d, ridx, t_st, rpts, s_var,
        Wg0, bg0, Wg1, bg1, Wg2, bg2, Wc0, bc0, out, n_rand, off_r);
    ray_starts<<<(n_rays + 256) / 256, 256>>>(ridx, n_rays, n_samples);
    composite<<<(n_rays * 32 + 255) / 256, 256>>>(t_st, out, n_rays, off_c, off_n, off_o, off_d, off_w);
}

// round 3
// speedup vs baseline: 1.3548x; 1.3548x over previous
#include <cuda_runtime.h>
#include <math.h>

#define PI_F 3.14159265358979323846f
#define NS_MAX 524288
#define NR_MAX 16384

typedef unsigned long long ull;

__device__ __forceinline__ ull dup2(float v) {
    ull r; asm("mov.b64 %0, {%1,%1};" : "=l"(r) : "f"(v)); return r;
}
__device__ __forceinline__ void fma2(ull& d, ull a, ull b) {
    asm("fma.rn.f32x2 %0, %1, %2, %0;" : "+l"(d) : "l"(a), "l"(b));
}
__device__ __forceinline__ float2 unp(ull v) {
    float lo, hi; asm("mov.b64 {%0,%1}, %2;" : "=f"(lo), "=f"(hi) : "l"(v));
    return make_float2(lo, hi);
}

// ---------------- device scratch ----------------
__device__ float g_Wg1T[256 * 256];
__device__ float g_Wg0T[256 * 40];
__device__ float g_Wc1p[256 * 4];
__device__ float g_bc1p[4];
__device__ float g_a[NS_MAX];
__device__ float g_loga[NS_MAX];
__device__ float g_rgb[NS_MAX * 3];
__device__ float g_nrm[NS_MAX * 3];
__device__ int   g_start[NR_MAX + 1];

// ---------------- smem layout (floats) ----------------
#define XS_OFF   0
#define H0_OFF   2560
#define H1_OFF   18944
#define WS_OFF   35328          // 2 x 16 x 264 = 8448 floats (weight tiles / reduction)
#define FS_OFF   43776
#define GX_OFF   44800
#define RGB_OFF  47360
#define PS_OFF   47616
#define DS_OFF   47808
#define NSM_OFF  48000
#define CIN_OFF  48192
#define SMEM_FLOATS 49792
#define SMEM_BYTES (SMEM_FLOATS * 4)

// epilogue: 0 relu+bias, 1 mask-by-existing, 2 bias, 3 sigmoid+bias
template <int EPI>
__device__ __forceinline__ void epi_store(float* p, float4 v, float b) {
    if (EPI == 1) {
        float4 d = *(const float4*)p;
        v.x = d.x > 0.f ? v.x : 0.f; v.y = d.y > 0.f ? v.y : 0.f;
        v.z = d.z > 0.f ? v.z : 0.f; v.w = d.w > 0.f ? v.w : 0.f;
    } else {
        v.x += b; v.y += b; v.z += b; v.w += b;
        if (EPI == 0) {
            v.x = fmaxf(v.x, 0.f); v.y = fmaxf(v.y, 0.f);
            v.z = fmaxf(v.z, 0.f); v.w = fmaxf(v.w, 0.f);
        }
        if (EPI == 3) {
            v.x = 1.f / (1.f + expf(-v.x)); v.y = 1.f / (1.f + expf(-v.y));
            v.z = 1.f / (1.f + expf(-v.z)); v.w = 1.f / (1.f + expf(-v.w));
        }
    }
    *(float4*)p = v;
}

#define KSTEP(Ap, Wp, kt) { \
    float4 a = *(const float4*)((Ap) + (kt) * 64); \
    ull a0 = dup2(a.x), a1 = dup2(a.y), a2 = dup2(a.z), a3 = dup2(a.w); \
    ulonglong2 w01 = *(const ulonglong2*)((Wp) + (kt) * 264); \
    ulonglong2 w23 = *(const ulonglong2*)((Wp) + (kt) * 264 + 4); \
    fma2(acc[0][0], a0, w01.x); fma2(acc[0][1], a0, w01.y); fma2(acc[0][2], a0, w23.x); fma2(acc[0][3], a0, w23.y); \
    fma2(acc[1][0], a1, w01.x); fma2(acc[1][1], a1, w01.y); fma2(acc[1][2], a1, w23.x); fma2(acc[1][3], a1, w23.y); \
    fma2(acc[2][0], a2, w01.x); fma2(acc[2][1], a2, w01.y); fma2(acc[2][2], a2, w23.x); fma2(acc[2][3], a2, w23.y); \
    fma2(acc[3][0], a3, w01.x); fma2(acc[3][1], a3, w01.y); fma2(acc[3][2], a3, w23.x); fma2(acc[3][3], a3, w23.y); }

// ---------------- wide GEMM: D[C<=256][64] = epi(A[K][64]^T @ W[K][C]), 512 thr ----
template <int EPI>
__device__ void gemm_wide(const float* As, const float* Wg, int ldw,
                          int K, int C, const float* bias,
                          float* Ds, float* Ws) {
    const int tid = threadIdx.x;
    const int tx = tid & 15;        // 4 samples
    const int ty = tid >> 4;        // 0..31 -> 8 cols
    ull acc[4][4];
#pragma unroll
    for (int i = 0; i < 4; i++)
#pragma unroll
        for (int j = 0; j < 4; j++) acc[i][j] = 0ull;

    const int ntiles = (K + 15) >> 4;
    float4 pre[2];
#pragma unroll
    for (int q = 0; q < 2; q++) {
        int idx = q * 512 + tid, r = idx >> 6, col = (idx & 63) * 4;
        float4 v = make_float4(0.f, 0.f, 0.f, 0.f);
        if (r < K && col < C) v = *(const float4*)(Wg + (size_t)r * ldw + col);
        pre[q] = v;
    }
    for (int t = 0; t < ntiles; t++) {
        float* buf = Ws + (t & 1) * 4224;
#pragma unroll
        for (int q = 0; q < 2; q++) {
            int idx = q * 512 + tid, r = idx >> 6, col = (idx & 63) * 4;
            *(float4*)(buf + r * 264 + col) = pre[q];
        }
        __syncthreads();
        if (t + 1 < ntiles) {
            int k0 = (t + 1) * 16;
#pragma unroll
            for (int q = 0; q < 2; q++) {
                int idx = q * 512 + tid, r = idx >> 6, col = (idx & 63) * 4;
                float4 v = make_float4(0.f, 0.f, 0.f, 0.f);
                if (k0 + r < K && col < C) v = *(const float4*)(Wg + (size_t)(k0 + r) * ldw + col);
                pre[q] = v;
            }
        }
        int klen = K - t * 16; if (klen > 16) klen = 16;
        const float* Ap = As + t * 16 * 64 + tx * 4;
        const float* Wp = buf + ty * 8;
        if (klen == 16) {
#pragma unroll
            for (int kt = 0; kt < 16; kt++) KSTEP(Ap, Wp, kt)
        } else {
            for (int kt = 0; kt < klen; kt++) KSTEP(Ap, Wp, kt)
        }
    }
#pragma unroll
    for (int jj = 0; jj < 4; jj++) {
        float2 v0 = unp(acc[0][jj]), v1 = unp(acc[1][jj]), v2 = unp(acc[2][jj]), v3 = unp(acc[3][jj]);
        int c = ty * 8 + jj * 2;
        if (c < C)     epi_store<EPI>(Ds + c * 64 + tx * 4,
                                      make_float4(v0.x, v1.x, v2.x, v3.x), bias ? bias[c] : 0.f);
        if (c + 1 < C) epi_store<EPI>(Ds + (c + 1) * 64 + tx * 4,
                                      make_float4(v0.y, v1.y, v2.y, v3.y), bias ? bias[c + 1] : 0.f);
    }
    __syncthreads();
}

// ---------------- narrow GEMM (C<=64): 4-way K-split + smem reduction ----------------
template <int EPI>
__device__ void gemm_narrow(const float* As, const float* Wg, int ldw,
                            int K, int C, const float* bias,
                            float* Ds, float* Ws) {
    const int tid = threadIdx.x;
    const int tx = tid & 15;
    const int tyc = (tid >> 4) & 7;   // 8 cols
    const int ks = tid >> 7;          // K slice 0..3
    ull acc[4][4];
#pragma unroll
    for (int i = 0; i < 4; i++)
#pragma unroll
        for (int j = 0; j < 4; j++) acc[i][j] = 0ull;

    const int ntiles = (K + 15) >> 4;
    const int tps = (ntiles + 3) >> 2;
    int myt = ntiles - ks * tps; myt = myt < 0 ? 0 : (myt > tps ? tps : myt);

    float4 pre[2];
#pragma unroll
    for (int q = 0; q < 2; q++) {
        int idx = q * 512 + tid;
        int col = (idx & 15) * 4, r = (idx >> 4) & 15, sl = idx >> 8;
        int grow = (sl * tps) * 16 + r;
        float4 v = make_float4(0.f, 0.f, 0.f, 0.f);
        if (sl * tps < ntiles && grow < K && col < C)
            v = *(const float4*)(Wg + (size_t)grow * ldw + col);
        pre[q] = v;
    }
    for (int t = 0; t < tps; t++) {
        float* buf = Ws + (t & 1) * 4224;
#pragma unroll
        for (int q = 0; q < 2; q++) {
            int idx = q * 512 + tid;
            int col = (idx & 15) * 4, r = (idx >> 4) & 15, sl = idx >> 8;
            *(float4*)(buf + r * 264 + sl * 64 + col) = pre[q];
        }
        __syncthreads();
        if (t + 1 < tps) {
#pragma unroll
            for (int q = 0; q < 2; q++) {
                int idx = q * 512 + tid;
                int col = (idx & 15) * 4, r = (idx >> 4) & 15, sl = idx >> 8;
                int grow = (sl * tps + t + 1) * 16 + r;
                float4 v = make_float4(0.f, 0.f, 0.f, 0.f);
                if (sl * tps + t + 1 < ntiles && grow < K && col < C)
                    v = *(const float4*)(Wg + (size_t)grow * ldw + col);
                pre[q] = v;
            }
        }
        if (t < myt) {
            int gk0 = (ks * tps + t) * 16;
            int klen = K - gk0; if (klen > 16) klen = 16;
            const float* Ap = As + gk0 * 64 + tx * 4;
            const float* Wp = buf + ks * 64 + tyc * 8;
            if (klen == 16) {
#pragma unroll
                for (int kt = 0; kt < 16; kt++) KSTEP(Ap, Wp, kt)
            } else {
                for (int kt = 0; kt < klen; kt++) KSTEP(Ap, Wp, kt)
            }
        }
    }
    __syncthreads();

    float vals[4][8];
#pragma unroll
    for (int i = 0; i < 4; i++)
#pragma unroll
        for (int jj = 0; jj < 4; jj++) {
            float2 v = unp(acc[i][jj]);
            vals[i][jj * 2] = v.x; vals[i][jj * 2 + 1] = v.y;
        }

    float* red = Ws;
    if (ks >= 2) {
#pragma unroll
        for (int j = 0; j < 8; j++)
            *(float4*)(red + (ks - 2) * 4096 + (tyc * 8 + j) * 64 + tx * 4) =
                make_float4(vals[0][j], vals[1][j], vals[2][j], vals[3][j]);
    }
    __syncthreads();
    if (ks < 2) {
#pragma unroll
        for (int j = 0; j < 8; j++) {
            float4 p = *(const float4*)(red + ks * 4096 + (tyc * 8 + j) * 64 + tx * 4);
            vals[0][j] += p.x; vals[1][j] += p.y; vals[2][j] += p.z; vals[3][j] += p.w;
        }
    }
    __syncthreads();
    if (ks == 1) {
#pragma unroll
        for (int j = 0; j < 8; j++)
            *(float4*)(red + (tyc * 8 + j) * 64 + tx * 4) =
                make_float4(vals[0][j], vals[1][j], vals[2][j], vals[3][j]);
    }
    __syncthreads();
    if (ks == 0) {
#pragma unroll
        for (int j = 0; j < 8; j++) {
            float4 p = *(const float4*)(red + (tyc * 8 + j) * 64 + tx * 4);
            vals[0][j] += p.x; vals[1][j] += p.y; vals[2][j] += p.z; vals[3][j] += p.w;
            int c = tyc * 8 + j;
            if (c < C)
                epi_store<EPI>(Ds + c * 64 + tx * 4,
                               make_float4(vals[0][j], vals[1][j], vals[2][j], vals[3][j]),
                               bias ? bias[c] : 0.f);
        }
    }
    __syncthreads();
}

// ---------------- K0: weight prep ----------------
__global__ void prep_weights(const float* __restrict__ Wg0, const float* __restrict__ Wg1,
                             const float* __restrict__ Wc1, const float* __restrict__ bc1) {
    int idx = blockIdx.x * 256 + threadIdx.x;   // 65536 threads
    g_Wg1T[idx] = Wg1[(idx & 255) * 256 + (idx >> 8)];
    if (idx < 10240) {
        int k = idx / 40, r = idx % 40;
        g_Wg0T[idx] = (r < 39) ? Wg0[r * 256 + k] : 0.f;
    }
    if (idx < 1024) {
        int k = idx >> 2, c = idx & 3;
        g_Wc1p[idx] = (c < 3) ? Wc1[k * 3 + c] : 0.f;
    }
    if (idx < 4) g_bc1p[idx] = (idx < 3) ? bc1[idx] : 0.f;
}

// ---------------- K1: fused per-sample pipeline ----------------
template <bool RAND>
__global__ void __launch_bounds__(512) fused_mlp(
    const float* __restrict__ rays_o, const float* __restrict__ rays_d,
    const int* __restrict__ ridx, const float* __restrict__ t_starts,
    const float* __restrict__ pts, const float* __restrict__ s_var,
    const float* __restrict__ Wg0, const float* __restrict__ bg0,
    const float* __restrict__ Wg1, const float* __restrict__ bg1,
    const float* __restrict__ Wg2, const float* __restrict__ bg2,
    const float* __restrict__ Wc0, const float* __restrict__ bc0,
    float* __restrict__ out, int n, long long off_sdf) {
    extern __shared__ float sm[];
    float* XS  = sm + XS_OFF;
    float* H0s = sm + H0_OFF;
    float* H1s = sm + H1_OFF;
    float* WS  = sm + WS_OFF;
    float* FS  = sm + FS_OFF;
    float* GX  = sm + GX_OFF;
    float* RGB = sm + RGB_OFF;
    float* PS  = sm + PS_OFF;
    float* DSH = sm + DS_OFF;
    float* NSM = sm + NSM_OFF;
    float* CIN = sm + CIN_OFF;

    const int tid = threadIdx.x;
    const int s0 = blockIdx.x * 64;
    const int s  = s0 + tid;
    const bool valid = (tid < 64) && (s < n);

    if (tid < 64) {
        int si = (s < n) ? s : (n - 1);
        float px, py, pz;
        if (RAND) {
            px = pts[si * 3 + 0]; py = pts[si * 3 + 1]; pz = pts[si * 3 + 2];
        } else {
            int ray = ridx[si];
            float ox = rays_o[ray * 3 + 0], oy = rays_o[ray * 3 + 1], oz = rays_o[ray * 3 + 2];
            float dx = rays_d[ray * 3 + 0], dy = rays_d[ray * 3 + 1], dz = rays_d[ray * 3 + 2];
            float inv = 1.f / (sqrtf(dx * dx + dy * dy + dz * dz) + 1e-10f);
            dx *= inv; dy *= inv; dz *= inv;
            float mid = t_starts[si] + 0.0025f;
            px = fmaf(dx, mid, ox); py = fmaf(dy, mid, oy); pz = fmaf(dz, mid, oz);
            PS[tid] = px; PS[64 + tid] = py; PS[128 + tid] = pz;
            DSH[tid] = dx; DSH[64 + tid] = dy; DSH[128 + tid] = dz;
        }
        XS[tid] = px; XS[64 + tid] = py; XS[128 + tid] = pz;
        float f = PI_F;
#pragma unroll
        for (int i = 0; i < 6; i++) {
            float sx, cx, sy, cy, sz, cz;
            sincosf(f * px, &sx, &cx);
            sincosf(f * py, &sy, &cy);
            sincosf(f * pz, &sz, &cz);
            XS[(3 + 6 * i) * 64 + tid] = sx;
            XS[(4 + 6 * i) * 64 + tid] = sy;
            XS[(5 + 6 * i) * 64 + tid] = sz;
            XS[(6 + 6 * i) * 64 + tid] = cx;
            XS[(7 + 6 * i) * 64 + tid] = cy;
            XS[(8 + 6 * i) * 64 + tid] = cz;
            f *= 2.f;
        }
    }
    __syncthreads();

    gemm_wide<0>(XS,  Wg0, 256, 39, 256, bg0, H0s, WS);
    gemm_wide<0>(H0s, Wg1, 256, 256, 256, bg1, H1s, WS);
    gemm_narrow<2>(H1s, Wg2, 16, 256, 16, bg2, FS, WS);

    if (RAND) {
        if (valid) out[off_sdf + s] = FS[tid];
        return;
    }

    // g1 = (h1>0) ? Wg2[:,0] : 0  (in place in H1s)
    for (int idx = tid; idx < 256 * 64; idx += 512)
        H1s[idx] = (H1s[idx] > 0.f) ? Wg2[(idx >> 6) * 16] : 0.f;
    __syncthreads();

    gemm_wide<1>(H1s, g_Wg1T, 256, 256, 256, 0, H0s, WS);   // g0 masked by h0>0
    gemm_narrow<2>(H0s, g_Wg0T, 40, 256, 39, 0, GX, WS);    // grad wrt posenc

    float inv_s = fminf(fmaxf(expf(s_var[0]), 1e-6f), 1e6f);
    if (tid < 64) {
        float gp[3];
#pragma unroll
        for (int d = 0; d < 3; d++) {
            float g = GX[d * 64 + tid];
            float f = PI_F;
#pragma unroll
            for (int i = 0; i < 6; i++) {
                float sn = XS[(3 + 6 * i + d) * 64 + tid];
                float cs = XS[(6 + 6 * i + d) * 64 + tid];
                float gs = GX[(3 + 6 * i + d) * 64 + tid];
                float gc = GX[(6 + 6 * i + d) * 64 + tid];
                g += f * (cs * gs - sn * gc);
                f *= 2.f;
            }
            gp[d] = g;
        }
        float len = sqrtf(gp[0] * gp[0] + gp[1] * gp[1] + gp[2] * gp[2]);
        float ninv = 1.f / (len + 1e-10f);
        float nx = gp[0] * ninv, ny = gp[1] * ninv, nz = gp[2] * ninv;
        NSM[tid] = nx; NSM[64 + tid] = ny; NSM[128 + tid] = nz;

        float dx = DSH[tid], dy = DSH[64 + tid], dz = DSH[128 + tid];
        float dsdf = fminf(gp[0] * dx + gp[1] * dy + gp[2] * dz, 0.f);
        float sdf = FS[tid];
        float cdf = 1.f / (1.f + expf(-inv_s * sdf));
        float rho = fmaxf(inv_s * (cdf - 1.f) * dsdf, 0.f);
        float alpha = 1.f - expf(-rho * 0.005f);
        float a = fminf(fmaxf(alpha, 0.f), 1.f - 1e-7f);
        if (valid) {
            g_a[s] = a;
            g_loga[s] = log1pf(-a);
            g_nrm[s * 3 + 0] = nx; g_nrm[s * 3 + 1] = ny; g_nrm[s * 3 + 2] = nz;
            out[off_sdf + s] = sdf;
        }
        // cin = [dir(3), feats(16), points(3), normal(3)]
        CIN[0 * 64 + tid] = dx; CIN[1 * 64 + tid] = dy; CIN[2 * 64 + tid] = dz;
#pragma unroll
        for (int c = 0; c < 16; c++) CIN[(3 + c) * 64 + tid] = FS[c * 64 + tid];
        CIN[19 * 64 + tid] = PS[tid]; CIN[20 * 64 + tid] = PS[64 + tid]; CIN[21 * 64 + tid] = PS[128 + tid];
        CIN[22 * 64 + tid] = nx; CIN[23 * 64 + tid] = ny; CIN[24 * 64 + tid] = nz;
    }
    __syncthreads();

    gemm_wide<0>(CIN, Wc0, 256, 25, 256, bc0, H1s, WS);
    gemm_narrow<3>(H1s, g_Wc1p, 4, 256, 4, g_bc1p, RGB, WS);

    if (valid) {
        g_rgb[s * 3 + 0] = RGB[0 * 64 + tid];
        g_rgb[s * 3 + 1] = RGB[1 * 64 + tid];
        g_rgb[s * 3 + 2] = RGB[2 * 64 + tid];
    }
}

// ---------------- K2: ray start offsets ----------------
__global__ void ray_starts(const int* __restrict__ ridx, int n_rays, int n_samples) {
    int r = blockIdx.x * 256 + threadIdx.x;
    if (r > n_rays) return;
    int lo = 0, hi = n_samples;
    while (lo < hi) { int m = (lo + hi) >> 1; if (ridx[m] < r) lo = m + 1; else hi = m; }
    g_start[r] = lo;
}

// ---------------- K3: per-ray scan + composite (warp per ray) ----------------
__global__ void composite(const float* __restrict__ t_starts, float* __restrict__ out,
                          int n_rays, long long off_c, long long off_n,
                          long long off_o, long long off_d, long long off_w) {
    int ray = (blockIdx.x * blockDim.x + threadIdx.x) >> 5;
    int lane = threadIdx.x & 31;
    if (ray >= n_rays) return;
    int s0 = g_start[ray], s1 = g_start[ray + 1];
    float carry = 0.f, op = 0.f, dep = 0.f;
    float c0 = 0.f, c1 = 0.f, c2 = 0.f, n0 = 0.f, n1 = 0.f, n2 = 0.f;
    for (int base = s0; base < s1; base += 32) {
        int s = base + lane;
        bool v = s < s1;
        float lg = v ? g_loga[s] : 0.f;
        float incl = lg;
#pragma unroll
        for (int o = 1; o < 32; o <<= 1) {
            float t = __shfl_up_sync(0xffffffffu, incl, o);
            if (lane >= o) incl += t;
        }
        if (v) {
            float w = g_a[s] * expf(carry + incl - lg);
            out[off_w + s] = w;
            float mid = t_starts[s] + 0.0025f;
            op += w; dep += w * mid;
            c0 += w * g_rgb[s * 3 + 0]; c1 += w * g_rgb[s * 3 + 1]; c2 += w * g_rgb[s * 3 + 2];
            n0 += w * g_nrm[s * 3 + 0]; n1 += w * g_nrm[s * 3 + 1]; n2 += w * g_nrm[s * 3 + 2];
        }
        carry += __shfl_sync(0xffffffffu, incl, 31);
    }
#pragma unroll
    for (int o = 16; o; o >>= 1) {
        op += __shfl_xor_sync(0xffffffffu, op, o);
        dep += __shfl_xor_sync(0xffffffffu, dep, o);
        c0 += __shfl_xor_sync(0xffffffffu, c0, o);
        c1 += __shfl_xor_sync(0xffffffffu, c1, o);
        c2 += __shfl_xor_sync(0xffffffffu, c2, o);
        n0 += __shfl_xor_sync(0xffffffffu, n0, o);
        n1 += __shfl_xor_sync(0xffffffffu, n1, o);
        n2 += __shfl_xor_sync(0xffffffffu, n2, o);
    }
    if (lane == 0) {
        out[off_o + ray] = op;
        out[off_d + ray] = dep;
        out[off_c + ray * 3 + 0] = c0; out[off_c + ray * 3 + 1] = c1; out[off_c + ray * 3 + 2] = c2;
        float nl = sqrtf(n0 * n0 + n1 * n1 + n2 * n2);
        float ninv = 1.f / (nl + 1e-10f);
        out[off_n + ray * 3 + 0] = n0 * ninv;
        out[off_n + ray * 3 + 1] = n1 * ninv;
        out[off_n + ray * 3 + 2] = n2 * ninv;
    }
}

extern "C" void kernel_launch(void* const* d_in, const int* in_sizes, int n_in,
                              void* d_out, int out_size) {
    const float* rays_o = (const float*)d_in[0];
    const float* rays_d = (const float*)d_in[1];
    const int*   ridx   = (const int*)d_in[2];
    const float* t_st   = (const float*)d_in[3];
    const float* rpts   = (const float*)d_in[4];
    const float* s_var  = (const float*)d_in[5];
    const float* Wg0 = (const float*)d_in[6];  const float* bg0 = (const float*)d_in[7];
    const float* Wg1 = (const float*)d_in[8];  const float* bg1 = (const float*)d_in[9];
    const float* Wg2 = (const float*)d_in[10]; const float* bg2 = (const float*)d_in[11];
    const float* Wc0 = (const float*)d_in[12]; const float* bc0 = (const float*)d_in[13];
    const float* Wc1 = (const float*)d_in[14]; const float* bc1 = (const float*)d_in[15];
    float* out = (float*)d_out;

    int n_rays = in_sizes[0] / 3;
    int n_samples = in_sizes[2];
    int n_rand = in_sizes[4] / 3;

    long long off_c = 0;
    long long off_n = off_c + 3LL * n_rays;
    long long off_o = off_n + 3LL * n_rays;
    long long off_d = off_o + n_rays;
    long long off_w = off_d + n_rays;
    long long off_s = off_w + n_samples;
    long long off_r = off_s + n_samples;

    cudaFuncSetAttribute(fused_mlp<false>, cudaFuncAttributeMaxDynamicSharedMemorySize, SMEM_BYTES);
    cudaFuncSetAttribute(fused_mlp<true>,  cudaFuncAttributeMaxDynamicSharedMemorySize, SMEM_BYTES);

    prep_weights<<<256, 256>>>(Wg0, Wg1, Wc1, bc1);
    fused_mlp<false><<<(n_samples + 63) / 64, 512, SMEM_BYTES>>>(
        rays_o, rays_d, ridx, t_st, rpts, s_var,
        Wg0, bg0, Wg1, bg1, Wg2, bg2, Wc0, bc0, out, n_samples, off_s);
    fused_mlp<true><<<(n_rand + 63) / 64, 512, SMEM_BYTES>>>(
        rays_o, rays_d, ridx, t_st, rpts, s_var,
        Wg0, bg0, Wg1, bg1, Wg2, bg2, Wc0, bc0, out, n_rand, off_r);
    ray_starts<<<(n_rays + 256) / 256, 256>>>(ridx, n_rays, n_samples);
    composite<<<(n_rays * 32 + 255) / 256, 256>>>(t_st, out, n_rays, off_c, off_n, off_o, off_d, off_w);
}